// round 2
// baseline (speedup 1.0000x reference)
#include <cuda_runtime.h>
#include <math.h>

#define HH   200
#define DD   300
#define TW   50
#define NS   2560
#define ND   256
#define DT   10
#define GG   600
#define GXW  1200
#define VOC  50000

// ---------------- device scratch ----------------
__device__ float g_P[VOC * GXW];        // emb @ [wf_ih; wb_ih]^T
__device__ float g_gxs[NS * GXW];       // sentence-level input gates
__device__ float g_wfhT[HH * GG];
__device__ float g_wbhT[HH * GG];
__device__ float g_sfhT[HH * GG];
__device__ float g_sbhT[HH * GG];
__device__ float g_hf[NS * HH];
__device__ float g_hb[NS * HH];
__device__ float g_pool[NS * 2 * HH];
__device__ float g_hsf[ND * HH];
__device__ float g_hsb[ND * HH];
__device__ float g_poold[ND * 2 * HH];
__device__ int   g_slen[NS];
__device__ int   g_offs[ND];

// ---------------- helpers ----------------
typedef unsigned long long ull;
__device__ __forceinline__ ull pack1(float a) {
    ull r; asm("mov.b64 %0, {%1, %1};" : "=l"(r) : "f"(a)); return r;
}
__device__ __forceinline__ void fma2(ull& d, ull a, ull b) {
    asm("fma.rn.f32x2 %0, %1, %2, %0;" : "+l"(d) : "l"(a), "l"(b));
}
__device__ __forceinline__ void unpack2(ull v, float& a, float& b) {
    asm("mov.b64 {%0, %1}, %2;" : "=f"(a), "=f"(b) : "l"(v));
}
__device__ __forceinline__ float sigmoidf_(float x) {
    return __fdividef(1.f, 1.f + __expf(-x));
}
__device__ __forceinline__ float tanhf_(float x) {
    return 2.f * __fdividef(1.f, 1.f + __expf(-2.f * x)) - 1.f;
}

// ---------------- C[M,N](ldc) = A[M,K] @ B[N,K]^T  (fp32, f32x2) ----------------
// 128x64 tile, BK=20, 256 threads, per-thread 8m x 4n.
__global__ __launch_bounds__(256) void gemm_bt(const float* __restrict__ A,
                                               const float* __restrict__ B,
                                               float* __restrict__ C,
                                               int M, int N, int K, int ldc) {
    __shared__ __align__(16) float As[20][132];
    __shared__ __align__(16) float Bs[20][68];
    int tid = threadIdx.x;
    int mb = blockIdx.y * 128, nb = blockIdx.x * 64;
    int tn = tid & 15, tm = tid >> 4;

    ull acc[4][4];
#pragma unroll
    for (int i = 0; i < 4; i++)
#pragma unroll
        for (int j = 0; j < 4; j++) acc[i][j] = 0ull;

    for (int k0 = 0; k0 < K; k0 += 20) {
#pragma unroll
        for (int l = 0; l < 10; l++) {
            int idx = tid + l * 256;
            int m = idx / 20, k = idx % 20;
            int gm = mb + m;
            As[k][m] = (gm < M) ? A[(size_t)gm * K + k0 + k] : 0.f;
        }
#pragma unroll
        for (int l = 0; l < 5; l++) {
            int idx = tid + l * 256;
            int n = idx / 20, k = idx % 20;
            int gn = nb + n;
            Bs[k][n] = (gn < N) ? B[(size_t)gn * K + k0 + k] : 0.f;
        }
        __syncthreads();
#pragma unroll
        for (int k = 0; k < 20; k++) {
            ulonglong2 a01 = *(const ulonglong2*)&As[k][tm * 8];
            ulonglong2 a23 = *(const ulonglong2*)&As[k][tm * 8 + 4];
            float4 bv = *(const float4*)&Bs[k][tn * 4];
            ull b0 = pack1(bv.x), b1 = pack1(bv.y), b2 = pack1(bv.z), b3 = pack1(bv.w);
            ull av[4] = {a01.x, a01.y, a23.x, a23.y};
#pragma unroll
            for (int i = 0; i < 4; i++) {
                fma2(acc[i][0], av[i], b0);
                fma2(acc[i][1], av[i], b1);
                fma2(acc[i][2], av[i], b2);
                fma2(acc[i][3], av[i], b3);
            }
        }
        __syncthreads();
    }
    int n0 = nb + tn * 4;
    if (n0 < N) {
#pragma unroll
        for (int i = 0; i < 4; i++) {
            int r0 = mb + tm * 8 + 2 * i;
            float v[2][4];
            unpack2(acc[i][0], v[0][0], v[1][0]);
            unpack2(acc[i][1], v[0][1], v[1][1]);
            unpack2(acc[i][2], v[0][2], v[1][2]);
            unpack2(acc[i][3], v[0][3], v[1][3]);
#pragma unroll
            for (int l = 0; l < 2; l++)
                if (r0 + l < M)
                    *(float4*)&C[(size_t)(r0 + l) * ldc + n0] =
                        make_float4(v[l][0], v[l][1], v[l][2], v[l][3]);
        }
    }
}

// ---------------- one GRU step, both dirs via blockIdx.y ----------------
template <int BROWS, bool WORD>
__global__ __launch_bounds__(256, 1) void gru_step(
    const int* __restrict__ toks, const int* __restrict__ dlens,
    const float* __restrict__ bi_f, const float* __restrict__ bh_f,
    const float* __restrict__ bi_b, const float* __restrict__ bh_b, int t) {
    constexpr int BP = BROWS / 2;
    constexpr int TLEN = WORD ? TW : DT;
    constexpr int NR = WORD ? NS : ND;
    const float* gxsrc = WORD ? g_P : g_gxs;
    float* pool = WORD ? g_pool : g_poold;

    __shared__ float2 hs[BP][HH];
    __shared__ int gxb[BROWS];
    __shared__ int sln[BROWS];

    int dir = blockIdx.y;
    int tt = dir ? (TLEN - 1 - t) : t;
    int b0 = blockIdx.x * BROWS;
    const float* whT = WORD ? (dir ? g_wbhT : g_wfhT) : (dir ? g_sbhT : g_sfhT);
    float* hg = WORD ? (dir ? g_hb : g_hf) : (dir ? g_hsb : g_hsf);
    const float* bi = dir ? bi_b : bi_f;
    const float* bh = dir ? bh_b : bh_f;

    int tid = threadIdx.x;
    for (int idx = tid; idx < BROWS * HH; idx += 256) {
        int b = idx / HH, j = idx % HH;
        int bg = b0 + b;
        float v = (bg < NR) ? hg[bg * HH + j] : 0.f;
        ((float*)hs)[(b >> 1) * (2 * HH) + 2 * j + (b & 1)] = v;
    }
    if (tid < BROWS) {
        int bg = b0 + tid;
        if (bg >= NR) bg = NR - 1;
        int row = WORD ? toks[bg * TLEN + tt] : (bg * TLEN + tt);
        gxb[tid] = row * GXW + dir * GG;
        sln[tid] = WORD ? g_slen[bg] : dlens[bg];
    }
    __syncthreads();

    int j = tid;
    if (j < HH) {
        ull aR[BP], aZ[BP], aN[BP];
#pragma unroll
        for (int p = 0; p < BP; p++) { aR[p] = 0; aZ[p] = 0; aN[p] = 0; }

#pragma unroll 2
        for (int k = 0; k < HH; k++) {
            const float* wk = whT + k * GG + j;
            ull w0 = pack1(wk[0]), w1 = pack1(wk[HH]), w2 = pack1(wk[2 * HH]);
#pragma unroll
            for (int p = 0; p < BP; p++) {
                ull hp = *(const ull*)&hs[p][k];
                fma2(aR[p], hp, w0);
                fma2(aZ[p], hp, w1);
                fma2(aN[p], hp, w2);
            }
        }

        float bij0 = bi[j], bij1 = bi[HH + j], bij2 = bi[2 * HH + j];
        float bhj0 = bh[j], bhj1 = bh[HH + j], bhj2 = bh[2 * HH + j];
        for (int p = 0; p < BP; p++) {
            float hr[2], hz[2], hn[2];
            unpack2(aR[p], hr[0], hr[1]);
            unpack2(aZ[p], hz[0], hz[1]);
            unpack2(aN[p], hn[0], hn[1]);
            float2 hold = hs[p][j];
#pragma unroll
            for (int l = 0; l < 2; l++) {
                int b = 2 * p + l;
                int bg = b0 + b;
                if (bg < NR) {
                    const float* gx = gxsrc + gxb[b];
                    float r = sigmoidf_(gx[j] + bij0 + hr[l] + bhj0);
                    float z = sigmoidf_(gx[HH + j] + bij1 + hz[l] + bhj1);
                    float nn = tanhf_(gx[2 * HH + j] + bij2 + r * (hn[l] + bhj2));
                    float ho = l ? hold.y : hold.x;
                    float hnew = (1.f - z) * nn + z * ho;
                    hg[bg * HH + j] = hnew;
                    if (tt < sln[b])
                        pool[bg * (2 * HH) + dir * HH + j] += hnew;
                }
            }
        }
    }
}

// ---------------- prep: transposes, sent lens, zero state ----------------
__global__ void k_prep(const int* __restrict__ x,
                       const float* __restrict__ wf_hh, const float* __restrict__ wb_hh,
                       const float* __restrict__ sf_hh, const float* __restrict__ sb_hh) {
    int i0 = blockIdx.x * blockDim.x + threadIdx.x;
    int gs = gridDim.x * blockDim.x;
    for (int idx = i0; idx < HH * GG; idx += gs) {
        int k = idx / GG, g = idx % GG;
        g_wfhT[idx] = wf_hh[g * HH + k];
        g_wbhT[idx] = wb_hh[g * HH + k];
        g_sfhT[idx] = sf_hh[g * HH + k];
        g_sbhT[idx] = sb_hh[g * HH + k];
    }
    for (int s = i0; s < NS; s += gs) {
        int c = 0;
        for (int t = 0; t < TW; t++) c += (x[s * TW + t] != 0);
        g_slen[s] = c;
    }
    for (int i = i0; i < NS * HH; i += gs) { g_hf[i] = 0.f; g_hb[i] = 0.f; }
    for (int i = i0; i < NS * 2 * HH; i += gs) g_pool[i] = 0.f;
    for (int i = i0; i < ND * HH; i += gs) { g_hsf[i] = 0.f; g_hsb[i] = 0.f; }
    for (int i = i0; i < ND * 2 * HH; i += gs) g_poold[i] = 0.f;
}

__global__ void k_div() {
    int i = blockIdx.x * blockDim.x + threadIdx.x;
    if (i < NS * 2 * HH) {
        int b = i / (2 * HH);
        int l = g_slen[b];
        g_pool[i] = l ? g_pool[i] / (float)l : 0.f;
    }
}

__global__ void k_scan(const int* __restrict__ dl) {
    if (threadIdx.x == 0) {
        int a = 0;
        for (int i = 0; i < ND; i++) { g_offs[i] = a; a += dl[i]; }
    }
}

__global__ __launch_bounds__(128) void k_final(const int* __restrict__ dl,
                                               const float* __restrict__ doc_w,
                                               const float* __restrict__ doc_b,
                                               const float* __restrict__ sent_w,
                                               const float* __restrict__ sent_b,
                                               float* __restrict__ out) {
    __shared__ float d[2 * HH];
    __shared__ float redw[4];
    int doc = blockIdx.x, tid = threadIdx.x;
    int l = dl[doc];
    for (int f = tid; f < 2 * HH; f += 128) {
        float v = g_poold[doc * 2 * HH + f];
        d[f] = l ? v / (float)l : 0.f;
    }
    __syncthreads();
    for (int r = 0; r < 11; r++) {
        const float* w = (r == 0) ? doc_w : sent_w + (r - 1) * 2 * HH;
        float p = 0.f;
        for (int f = tid; f < 2 * HH; f += 128) p += d[f] * w[f];
        for (int o = 16; o; o >>= 1) p += __shfl_down_sync(0xFFFFFFFFu, p, o);
        if ((tid & 31) == 0) redw[tid >> 5] = p;
        __syncthreads();
        if (tid == 0) {
            float s = redw[0] + redw[1] + redw[2] + redw[3];
            if (r == 0) out[doc] = sigmoidf_(s + doc_b[0]);
            else if (r - 1 < l) out[ND + g_offs[doc] + (r - 1)] = sigmoidf_(s + sent_b[r - 1]);
        }
        __syncthreads();
    }
}

// ---------------- host ----------------
extern "C" void kernel_launch(void* const* d_in, const int* in_sizes, int n_in,
                              void* d_out, int out_size) {
    int base = (n_in >= 24) ? 1 : 0;  // doc_nums scalar present or not
    const int*   x        = (const int*)d_in[0];
    const int*   doc_lens = (const int*)d_in[1 + base];
    const float* emb      = (const float*)d_in[2 + base];
    const float* wf_ih    = (const float*)d_in[3 + base];
    const float* wf_hh    = (const float*)d_in[4 + base];
    const float* wf_bi    = (const float*)d_in[5 + base];
    const float* wf_bh    = (const float*)d_in[6 + base];
    const float* wb_ih    = (const float*)d_in[7 + base];
    const float* wb_hh    = (const float*)d_in[8 + base];
    const float* wb_bi    = (const float*)d_in[9 + base];
    const float* wb_bh    = (const float*)d_in[10 + base];
    const float* sf_ih    = (const float*)d_in[11 + base];
    const float* sf_hh    = (const float*)d_in[12 + base];
    const float* sf_bi    = (const float*)d_in[13 + base];
    const float* sf_bh    = (const float*)d_in[14 + base];
    const float* sb_ih    = (const float*)d_in[15 + base];
    const float* sb_hh    = (const float*)d_in[16 + base];
    const float* sb_bi    = (const float*)d_in[17 + base];
    const float* sb_bh    = (const float*)d_in[18 + base];
    const float* doc_w    = (const float*)d_in[19 + base];
    const float* doc_b    = (const float*)d_in[20 + base];
    const float* sent_w   = (const float*)d_in[21 + base];
    const float* sent_b   = (const float*)d_in[22 + base];
    float* out = (float*)d_out;

    float *P, *gxs, *pool;
    cudaGetSymbolAddress((void**)&P, g_P);
    cudaGetSymbolAddress((void**)&gxs, g_gxs);
    cudaGetSymbolAddress((void**)&pool, g_pool);

    k_prep<<<256, 256>>>(x, wf_hh, wb_hh, sf_hh, sb_hh);

    // P = emb @ [wf_ih; wb_ih]^T   (50000 x 1200)
    dim3 gP((600 + 63) / 64, (VOC + 127) / 128);
    gemm_bt<<<gP, 256>>>(emb, wf_ih, P, VOC, 600, DD, GXW);
    gemm_bt<<<gP, 256>>>(emb, wb_ih, P + 600, VOC, 600, DD, GXW);

    // word-level BiGRU: 50 steps
    dim3 gW((NS + 35) / 36, 2);
    for (int t = 0; t < TW; t++)
        gru_step<36, true><<<gW, 256>>>(x, doc_lens, wf_bi, wf_bh, wb_bi, wb_bh, t);

    k_div<<<(NS * 2 * HH + 255) / 256, 256>>>();

    // sentence-level gates: gxs = s @ [sf_ih; sb_ih]^T   (2560 x 1200, K=400)
    dim3 gS((600 + 63) / 64, (NS + 127) / 128);
    gemm_bt<<<gS, 256>>>(pool, sf_ih, gxs, NS, 600, 2 * HH, GXW);
    gemm_bt<<<gS, 256>>>(pool, sb_ih, gxs + 600, NS, 600, 2 * HH, GXW);

    // sentence-level BiGRU: 10 steps
    dim3 gD((ND + 7) / 8, 2);
    for (int t = 0; t < DT; t++)
        gru_step<8, false><<<gD, 256>>>(nullptr, doc_lens, sf_bi, sf_bh, sb_bi, sb_bh, t);

    k_scan<<<1, 32>>>(doc_lens);
    k_final<<<ND, 128>>>(doc_lens, doc_w, doc_b, sent_w, sent_b, out);
}

// round 3
// speedup vs baseline: 1.1352x; 1.1352x over previous
#include <cuda_runtime.h>
#include <math.h>

#define HH   200
#define DD   300
#define TW   50
#define NS   2560
#define ND   256
#define DT   10
#define GG   600
#define GXW  1200
#define VOC  50000

// ---------------- device scratch ----------------
__device__ float g_P[VOC * GXW];        // emb @ [wf_ih; wb_ih]^T
__device__ float g_gxs[NS * GXW];       // sentence-level input gates
__device__ float g_wfhT[HH * GG];
__device__ float g_wbhT[HH * GG];
__device__ float g_sfhT[HH * GG];
__device__ float g_sbhT[HH * GG];
__device__ float g_hf[NS * HH];
__device__ float g_hb[NS * HH];
__device__ float g_pool[NS * 2 * HH];
__device__ float g_hsf[ND * HH];
__device__ float g_hsb[ND * HH];
__device__ float g_poold[ND * 2 * HH];
__device__ int   g_slen[NS];
__device__ int   g_offs[ND];

// ---------------- helpers ----------------
typedef unsigned long long ull;
__device__ __forceinline__ ull pack1(float a) {
    ull r; asm("mov.b64 %0, {%1, %1};" : "=l"(r) : "f"(a)); return r;
}
__device__ __forceinline__ void fma2(ull& d, ull a, ull b) {
    asm("fma.rn.f32x2 %0, %1, %2, %0;" : "+l"(d) : "l"(a), "l"(b));
}
__device__ __forceinline__ void unpack2(ull v, float& a, float& b) {
    asm("mov.b64 {%0, %1}, %2;" : "=f"(a), "=f"(b) : "l"(v));
}
__device__ __forceinline__ float sigmoidf_(float x) {
    return __fdividef(1.f, 1.f + __expf(-x));
}
__device__ __forceinline__ float tanhf_(float x) {
    return 2.f * __fdividef(1.f, 1.f + __expf(-2.f * x)) - 1.f;
}

// ---------------- C[M,N](ldc) = A[M,K] @ B[N,K]^T  (fp32, f32x2) ----------------
// 128x64 tile, BK=20, 256 threads, per-thread 8m x 4n.
__global__ __launch_bounds__(256) void gemm_bt(const float* __restrict__ A,
                                               const float* __restrict__ B,
                                               float* __restrict__ C,
                                               int M, int N, int K, int ldc) {
    __shared__ __align__(16) float As[20][132];
    __shared__ __align__(16) float Bs[20][68];
    int tid = threadIdx.x;
    int mb = blockIdx.y * 128, nb = blockIdx.x * 64;
    int tn = tid & 15, tm = tid >> 4;

    ull acc[4][4];
#pragma unroll
    for (int i = 0; i < 4; i++)
#pragma unroll
        for (int j = 0; j < 4; j++) acc[i][j] = 0ull;

    for (int k0 = 0; k0 < K; k0 += 20) {
#pragma unroll
        for (int l = 0; l < 10; l++) {
            int idx = tid + l * 256;
            int m = idx / 20, k = idx % 20;
            int gm = mb + m;
            As[k][m] = (gm < M) ? A[(size_t)gm * K + k0 + k] : 0.f;
        }
#pragma unroll
        for (int l = 0; l < 5; l++) {
            int idx = tid + l * 256;
            int n = idx / 20, k = idx % 20;
            int gn = nb + n;
            Bs[k][n] = (gn < N) ? B[(size_t)gn * K + k0 + k] : 0.f;
        }
        __syncthreads();
#pragma unroll
        for (int k = 0; k < 20; k++) {
            ulonglong2 a01 = *(const ulonglong2*)&As[k][tm * 8];
            ulonglong2 a23 = *(const ulonglong2*)&As[k][tm * 8 + 4];
            float4 bv = *(const float4*)&Bs[k][tn * 4];
            ull b0 = pack1(bv.x), b1 = pack1(bv.y), b2 = pack1(bv.z), b3 = pack1(bv.w);
            ull av[4] = {a01.x, a01.y, a23.x, a23.y};
#pragma unroll
            for (int i = 0; i < 4; i++) {
                fma2(acc[i][0], av[i], b0);
                fma2(acc[i][1], av[i], b1);
                fma2(acc[i][2], av[i], b2);
                fma2(acc[i][3], av[i], b3);
            }
        }
        __syncthreads();
    }
    int n0 = nb + tn * 4;
    if (n0 < N) {
#pragma unroll
        for (int i = 0; i < 4; i++) {
            int r0 = mb + tm * 8 + 2 * i;
            float v[2][4];
            unpack2(acc[i][0], v[0][0], v[1][0]);
            unpack2(acc[i][1], v[0][1], v[1][1]);
            unpack2(acc[i][2], v[0][2], v[1][2]);
            unpack2(acc[i][3], v[0][3], v[1][3]);
#pragma unroll
            for (int l = 0; l < 2; l++)
                if (r0 + l < M)
                    *(float4*)&C[(size_t)(r0 + l) * ldc + n0] =
                        make_float4(v[l][0], v[l][1], v[l][2], v[l][3]);
        }
    }
}

// ---------------- one GRU step, both dirs via blockIdx.y ----------------
// BROWS small enough that 2 blocks fit per SM (latency hiding).
template <int BROWS, bool WORD, int MINB>
__global__ __launch_bounds__(256, MINB) void gru_step(
    const int* __restrict__ toks, const int* __restrict__ dlens,
    const float* __restrict__ bi_f, const float* __restrict__ bh_f,
    const float* __restrict__ bi_b, const float* __restrict__ bh_b, int t) {
    constexpr int BP = BROWS / 2;
    constexpr int TLEN = WORD ? TW : DT;
    constexpr int NR = WORD ? NS : ND;
    const float* gxsrc = WORD ? g_P : g_gxs;
    float* pool = WORD ? g_pool : g_poold;

    __shared__ float2 hs[BP][HH];
    __shared__ int gxb[BROWS];
    __shared__ int sln[BROWS];

    int dir = blockIdx.y;
    int tt = dir ? (TLEN - 1 - t) : t;
    int b0 = blockIdx.x * BROWS;
    const float* whT = WORD ? (dir ? g_wbhT : g_wfhT) : (dir ? g_sbhT : g_sfhT);
    float* hg = WORD ? (dir ? g_hb : g_hf) : (dir ? g_hsb : g_hsf);
    const float* bi = dir ? bi_b : bi_f;
    const float* bh = dir ? bh_b : bh_f;

    int tid = threadIdx.x;
    for (int idx = tid; idx < BROWS * HH; idx += 256) {
        int b = idx / HH, j = idx % HH;
        int bg = b0 + b;
        float v = (bg < NR) ? hg[bg * HH + j] : 0.f;
        ((float*)hs)[(b >> 1) * (2 * HH) + 2 * j + (b & 1)] = v;
    }
    if (tid < BROWS) {
        int bg = b0 + tid;
        if (bg >= NR) bg = NR - 1;
        int row = WORD ? toks[bg * TLEN + tt] : (bg * TLEN + tt);
        gxb[tid] = row * GXW + dir * GG;
        sln[tid] = WORD ? g_slen[bg] : dlens[bg];
    }
    __syncthreads();

    int j = tid;
    if (j < HH) {
        ull aR[BP], aZ[BP], aN[BP];
#pragma unroll
        for (int p = 0; p < BP; p++) { aR[p] = 0; aZ[p] = 0; aN[p] = 0; }

#pragma unroll 2
        for (int k = 0; k < HH; k++) {
            const float* wk = whT + k * GG + j;
            ull w0 = pack1(wk[0]), w1 = pack1(wk[HH]), w2 = pack1(wk[2 * HH]);
#pragma unroll
            for (int p = 0; p < BP; p++) {
                ull hp = *(const ull*)&hs[p][k];
                fma2(aR[p], hp, w0);
                fma2(aZ[p], hp, w1);
                fma2(aN[p], hp, w2);
            }
        }

        float bij0 = bi[j], bij1 = bi[HH + j], bij2 = bi[2 * HH + j];
        float bhj0 = bh[j], bhj1 = bh[HH + j], bhj2 = bh[2 * HH + j];
        for (int p = 0; p < BP; p++) {
            float hr[2], hz[2], hn[2];
            unpack2(aR[p], hr[0], hr[1]);
            unpack2(aZ[p], hz[0], hz[1]);
            unpack2(aN[p], hn[0], hn[1]);
            float2 hold = hs[p][j];
#pragma unroll
            for (int l = 0; l < 2; l++) {
                int b = 2 * p + l;
                int bg = b0 + b;
                if (bg < NR) {
                    const float* gx = gxsrc + gxb[b];
                    float r = sigmoidf_(gx[j] + bij0 + hr[l] + bhj0);
                    float z = sigmoidf_(gx[HH + j] + bij1 + hz[l] + bhj1);
                    float nn = tanhf_(gx[2 * HH + j] + bij2 + r * (hn[l] + bhj2));
                    float ho = l ? hold.y : hold.x;
                    float hnew = (1.f - z) * nn + z * ho;
                    hg[bg * HH + j] = hnew;
                    if (tt < sln[b])
                        pool[bg * (2 * HH) + dir * HH + j] += hnew;
                }
            }
        }
    }
}

// ---------------- prep: transposes, sent lens, zero state ----------------
__global__ void k_prep(const int* __restrict__ x,
                       const float* __restrict__ wf_hh, const float* __restrict__ wb_hh,
                       const float* __restrict__ sf_hh, const float* __restrict__ sb_hh) {
    int i0 = blockIdx.x * blockDim.x + threadIdx.x;
    int gs = gridDim.x * blockDim.x;
    for (int idx = i0; idx < HH * GG; idx += gs) {
        int k = idx / GG, g = idx % GG;
        g_wfhT[idx] = wf_hh[g * HH + k];
        g_wbhT[idx] = wb_hh[g * HH + k];
        g_sfhT[idx] = sf_hh[g * HH + k];
        g_sbhT[idx] = sb_hh[g * HH + k];
    }
    for (int s = i0; s < NS; s += gs) {
        int c = 0;
        for (int t = 0; t < TW; t++) c += (x[s * TW + t] != 0);
        g_slen[s] = c;
    }
    for (int i = i0; i < NS * HH; i += gs) { g_hf[i] = 0.f; g_hb[i] = 0.f; }
    for (int i = i0; i < NS * 2 * HH; i += gs) g_pool[i] = 0.f;
    for (int i = i0; i < ND * HH; i += gs) { g_hsf[i] = 0.f; g_hsb[i] = 0.f; }
    for (int i = i0; i < ND * 2 * HH; i += gs) g_poold[i] = 0.f;
}

__global__ void k_div() {
    int i = blockIdx.x * blockDim.x + threadIdx.x;
    if (i < NS * 2 * HH) {
        int b = i / (2 * HH);
        int l = g_slen[b];
        g_pool[i] = l ? g_pool[i] / (float)l : 0.f;
    }
}

__global__ void k_scan(const int* __restrict__ dl) {
    if (threadIdx.x == 0) {
        int a = 0;
        for (int i = 0; i < ND; i++) { g_offs[i] = a; a += dl[i]; }
    }
}

__global__ __launch_bounds__(128) void k_final(const int* __restrict__ dl,
                                               const float* __restrict__ doc_w,
                                               const float* __restrict__ doc_b,
                                               const float* __restrict__ sent_w,
                                               const float* __restrict__ sent_b,
                                               float* __restrict__ out) {
    __shared__ float d[2 * HH];
    __shared__ float redw[4];
    int doc = blockIdx.x, tid = threadIdx.x;
    int l = dl[doc];
    for (int f = tid; f < 2 * HH; f += 128) {
        float v = g_poold[doc * 2 * HH + f];
        d[f] = l ? v / (float)l : 0.f;
    }
    __syncthreads();
    for (int r = 0; r < 11; r++) {
        const float* w = (r == 0) ? doc_w : sent_w + (r - 1) * 2 * HH;
        float p = 0.f;
        for (int f = tid; f < 2 * HH; f += 128) p += d[f] * w[f];
        for (int o = 16; o; o >>= 1) p += __shfl_down_sync(0xFFFFFFFFu, p, o);
        if ((tid & 31) == 0) redw[tid >> 5] = p;
        __syncthreads();
        if (tid == 0) {
            float s = redw[0] + redw[1] + redw[2] + redw[3];
            if (r == 0) out[doc] = sigmoidf_(s + doc_b[0]);
            else if (r - 1 < l) out[ND + g_offs[doc] + (r - 1)] = sigmoidf_(s + sent_b[r - 1]);
        }
        __syncthreads();
    }
}

// ---------------- host ----------------
extern "C" void kernel_launch(void* const* d_in, const int* in_sizes, int n_in,
                              void* d_out, int out_size) {
    int base = (n_in >= 24) ? 1 : 0;  // doc_nums scalar present or not
    const int*   x        = (const int*)d_in[0];
    const int*   doc_lens = (const int*)d_in[1 + base];
    const float* emb      = (const float*)d_in[2 + base];
    const float* wf_ih    = (const float*)d_in[3 + base];
    const float* wf_hh    = (const float*)d_in[4 + base];
    const float* wf_bi    = (const float*)d_in[5 + base];
    const float* wf_bh    = (const float*)d_in[6 + base];
    const float* wb_ih    = (const float*)d_in[7 + base];
    const float* wb_hh    = (const float*)d_in[8 + base];
    const float* wb_bi    = (const float*)d_in[9 + base];
    const float* wb_bh    = (const float*)d_in[10 + base];
    const float* sf_ih    = (const float*)d_in[11 + base];
    const float* sf_hh    = (const float*)d_in[12 + base];
    const float* sf_bi    = (const float*)d_in[13 + base];
    const float* sf_bh    = (const float*)d_in[14 + base];
    const float* sb_ih    = (const float*)d_in[15 + base];
    const float* sb_hh    = (const float*)d_in[16 + base];
    const float* sb_bi    = (const float*)d_in[17 + base];
    const float* sb_bh    = (const float*)d_in[18 + base];
    const float* doc_w    = (const float*)d_in[19 + base];
    const float* doc_b    = (const float*)d_in[20 + base];
    const float* sent_w   = (const float*)d_in[21 + base];
    const float* sent_b   = (const float*)d_in[22 + base];
    float* out = (float*)d_out;

    float *P, *gxs, *pool;
    cudaGetSymbolAddress((void**)&P, g_P);
    cudaGetSymbolAddress((void**)&gxs, g_gxs);
    cudaGetSymbolAddress((void**)&pool, g_pool);

    k_prep<<<256, 256>>>(x, wf_hh, wb_hh, sf_hh, sb_hh);

    // P = emb @ [wf_ih; wb_ih]^T   (50000 x 1200)
    dim3 gP((600 + 63) / 64, (VOC + 127) / 128);
    gemm_bt<<<gP, 256>>>(emb, wf_ih, P, VOC, 600, DD, GXW);
    gemm_bt<<<gP, 256>>>(emb, wb_ih, P + 600, VOC, 600, DD, GXW);

    // word-level BiGRU: 50 steps  (BROWS=20 -> 128x2 blocks, 2 blocks/SM)
    dim3 gW((NS + 19) / 20, 2);
    for (int t = 0; t < TW; t++)
        gru_step<20, true, 2><<<gW, 256>>>(x, doc_lens, wf_bi, wf_bh, wb_bi, wb_bh, t);

    k_div<<<(NS * 2 * HH + 255) / 256, 256>>>();

    // sentence-level gates: gxs = s @ [sf_ih; sb_ih]^T   (2560 x 1200, K=400)
    dim3 gS((600 + 63) / 64, (NS + 127) / 128);
    gemm_bt<<<gS, 256>>>(pool, sf_ih, gxs, NS, 600, 2 * HH, GXW);
    gemm_bt<<<gS, 256>>>(pool, sb_ih, gxs + 600, NS, 600, 2 * HH, GXW);

    // sentence-level BiGRU: 10 steps
    dim3 gD((ND + 7) / 8, 2);
    for (int t = 0; t < DT; t++)
        gru_step<8, false, 1><<<gD, 256>>>(nullptr, doc_lens, sf_bi, sf_bh, sb_bi, sb_bh, t);

    k_scan<<<1, 32>>>(doc_lens);
    k_final<<<ND, 128>>>(doc_lens, doc_w, doc_b, sent_w, sent_b, out);
}

// round 4
// speedup vs baseline: 1.2905x; 1.1369x over previous
#include <cuda_runtime.h>
#include <math.h>

#define HH   200
#define DD   300
#define TW   50
#define NS   2560
#define ND   256
#define DT   10
#define GG   600
#define GXW  1200
#define VOC  50000

// ---------------- device scratch ----------------
__device__ float g_P[VOC * GXW];        // emb @ [wf_ih; wb_ih]^T
__device__ float g_gxs[NS * GXW];       // sentence-level input gates
// packed recurrent weights: [k][j] -> float4(w_r, w_z, w_n, 0)
__device__ float4 g_wfhP[HH * HH];
__device__ float4 g_wbhP[HH * HH];
__device__ float4 g_sfhP[HH * HH];
__device__ float4 g_sbhP[HH * HH];
__device__ float g_hf[NS * HH];
__device__ float g_hb[NS * HH];
__device__ float g_pool[NS * 2 * HH];
__device__ float g_hsf[ND * HH];
__device__ float g_hsb[ND * HH];
__device__ float g_poold[ND * 2 * HH];
__device__ int   g_slen[NS];
__device__ int   g_offs[ND];

// ---------------- helpers ----------------
typedef unsigned long long ull;
__device__ __forceinline__ ull pack1(float a) {
    ull r; asm("mov.b64 %0, {%1, %1};" : "=l"(r) : "f"(a)); return r;
}
__device__ __forceinline__ void fma2(ull& d, ull a, ull b) {
    asm("fma.rn.f32x2 %0, %1, %2, %0;" : "+l"(d) : "l"(a), "l"(b));
}
__device__ __forceinline__ void unpack2(ull v, float& a, float& b) {
    asm("mov.b64 {%0, %1}, %2;" : "=f"(a), "=f"(b) : "l"(v));
}
__device__ __forceinline__ float sigmoidf_(float x) {
    return __fdividef(1.f, 1.f + __expf(-x));
}
__device__ __forceinline__ float tanhf_(float x) {
    return 2.f * __fdividef(1.f, 1.f + __expf(-2.f * x)) - 1.f;
}

// ---------------- C[M,N](ldc) = A[M,K] @ B[N,K]^T  (fp32, f32x2) ----------------
__global__ __launch_bounds__(256) void gemm_bt(const float* __restrict__ A,
                                               const float* __restrict__ B,
                                               float* __restrict__ C,
                                               int M, int N, int K, int ldc) {
    __shared__ __align__(16) float As[20][132];
    __shared__ __align__(16) float Bs[20][68];
    int tid = threadIdx.x;
    int mb = blockIdx.y * 128, nb = blockIdx.x * 64;
    int tn = tid & 15, tm = tid >> 4;

    ull acc[4][4];
#pragma unroll
    for (int i = 0; i < 4; i++)
#pragma unroll
        for (int j = 0; j < 4; j++) acc[i][j] = 0ull;

    for (int k0 = 0; k0 < K; k0 += 20) {
#pragma unroll
        for (int l = 0; l < 10; l++) {
            int idx = tid + l * 256;
            int m = idx / 20, k = idx % 20;
            int gm = mb + m;
            As[k][m] = (gm < M) ? A[(size_t)gm * K + k0 + k] : 0.f;
        }
#pragma unroll
        for (int l = 0; l < 5; l++) {
            int idx = tid + l * 256;
            int n = idx / 20, k = idx % 20;
            int gn = nb + n;
            Bs[k][n] = (gn < N) ? B[(size_t)gn * K + k0 + k] : 0.f;
        }
        __syncthreads();
#pragma unroll
        for (int k = 0; k < 20; k++) {
            ulonglong2 a01 = *(const ulonglong2*)&As[k][tm * 8];
            ulonglong2 a23 = *(const ulonglong2*)&As[k][tm * 8 + 4];
            float4 bv = *(const float4*)&Bs[k][tn * 4];
            ull b0 = pack1(bv.x), b1 = pack1(bv.y), b2 = pack1(bv.z), b3 = pack1(bv.w);
            ull av[4] = {a01.x, a01.y, a23.x, a23.y};
#pragma unroll
            for (int i = 0; i < 4; i++) {
                fma2(acc[i][0], av[i], b0);
                fma2(acc[i][1], av[i], b1);
                fma2(acc[i][2], av[i], b2);
                fma2(acc[i][3], av[i], b3);
            }
        }
        __syncthreads();
    }
    int n0 = nb + tn * 4;
    if (n0 < N) {
#pragma unroll
        for (int i = 0; i < 4; i++) {
            int r0 = mb + tm * 8 + 2 * i;
            float v[2][4];
            unpack2(acc[i][0], v[0][0], v[1][0]);
            unpack2(acc[i][1], v[0][1], v[1][1]);
            unpack2(acc[i][2], v[0][2], v[1][2]);
            unpack2(acc[i][3], v[0][3], v[1][3]);
#pragma unroll
            for (int l = 0; l < 2; l++)
                if (r0 + l < M)
                    *(float4*)&C[(size_t)(r0 + l) * ldc + n0] =
                        make_float4(v[l][0], v[l][1], v[l][2], v[l][3]);
        }
    }
}

// ---------------- one GRU step, both dirs via blockIdx.y ----------------
// Packed float4 weights + depth-4 register prefetch pipeline.
template <int BROWS, bool WORD, int MINB>
__global__ __launch_bounds__(256, MINB) void gru_step(
    const int* __restrict__ toks, const int* __restrict__ dlens,
    const float* __restrict__ bi_f, const float* __restrict__ bh_f,
    const float* __restrict__ bi_b, const float* __restrict__ bh_b, int t) {
    constexpr int BP = BROWS / 2;
    constexpr int TLEN = WORD ? TW : DT;
    constexpr int NR = WORD ? NS : ND;
    const float* gxsrc = WORD ? g_P : g_gxs;
    float* pool = WORD ? g_pool : g_poold;

    __shared__ float2 hs[BP][HH];
    __shared__ int gxb[BROWS];
    __shared__ int sln[BROWS];

    int dir = blockIdx.y;
    int tt = dir ? (TLEN - 1 - t) : t;
    int b0 = blockIdx.x * BROWS;
    const float4* wP = WORD ? (dir ? g_wbhP : g_wfhP) : (dir ? g_sbhP : g_sfhP);
    float* hg = WORD ? (dir ? g_hb : g_hf) : (dir ? g_hsb : g_hsf);
    const float* bi = dir ? bi_b : bi_f;
    const float* bh = dir ? bh_b : bh_f;

    int tid = threadIdx.x;
    for (int idx = tid; idx < BROWS * HH; idx += 256) {
        int b = idx / HH, j = idx % HH;
        int bg = b0 + b;
        float v = (bg < NR) ? hg[bg * HH + j] : 0.f;
        ((float*)hs)[(b >> 1) * (2 * HH) + 2 * j + (b & 1)] = v;
    }
    if (tid < BROWS) {
        int bg = b0 + tid;
        if (bg >= NR) bg = NR - 1;
        int row = WORD ? toks[bg * TLEN + tt] : (bg * TLEN + tt);
        gxb[tid] = row * GXW + dir * GG;
        sln[tid] = WORD ? g_slen[bg] : dlens[bg];
    }
    __syncthreads();

    int j = tid;
    if (j < HH) {
        ull aR[BP], aZ[BP], aN[BP];
#pragma unroll
        for (int p = 0; p < BP; p++) { aR[p] = 0; aZ[p] = 0; aN[p] = 0; }

        const float4* wp = wP + j;   // stride HH between k's
        float4 wreg[4];
#pragma unroll
        for (int i = 0; i < 4; i++) wreg[i] = wp[i * HH];

#pragma unroll 4
        for (int k = 0; k < HH; k++) {
            float4 wc = wreg[k & 3];
            int kp = k + 4;
            if (kp < HH) wreg[k & 3] = wp[kp * HH];
            ull w0 = pack1(wc.x), w1 = pack1(wc.y), w2 = pack1(wc.z);
#pragma unroll
            for (int p = 0; p < BP; p++) {
                ull hp = *(const ull*)&hs[p][k];
                fma2(aR[p], hp, w0);
                fma2(aZ[p], hp, w1);
                fma2(aN[p], hp, w2);
            }
        }

        float bij0 = bi[j], bij1 = bi[HH + j], bij2 = bi[2 * HH + j];
        float bhj0 = bh[j], bhj1 = bh[HH + j], bhj2 = bh[2 * HH + j];
        for (int p = 0; p < BP; p++) {
            float hr[2], hz[2], hn[2];
            unpack2(aR[p], hr[0], hr[1]);
            unpack2(aZ[p], hz[0], hz[1]);
            unpack2(aN[p], hn[0], hn[1]);
            float2 hold = hs[p][j];
#pragma unroll
            for (int l = 0; l < 2; l++) {
                int b = 2 * p + l;
                int bg = b0 + b;
                if (bg < NR) {
                    const float* gx = gxsrc + gxb[b];
                    float r = sigmoidf_(gx[j] + bij0 + hr[l] + bhj0);
                    float z = sigmoidf_(gx[HH + j] + bij1 + hz[l] + bhj1);
                    float nn = tanhf_(gx[2 * HH + j] + bij2 + r * (hn[l] + bhj2));
                    float ho = l ? hold.y : hold.x;
                    float hnew = (1.f - z) * nn + z * ho;
                    hg[bg * HH + j] = hnew;
                    if (tt < sln[b])
                        pool[bg * (2 * HH) + dir * HH + j] += hnew;
                }
            }
        }
    }
}

// ---------------- prep: weight packing, sent lens, zero state ----------------
__global__ void k_prep(const int* __restrict__ x,
                       const float* __restrict__ wf_hh, const float* __restrict__ wb_hh,
                       const float* __restrict__ sf_hh, const float* __restrict__ sb_hh) {
    int i0 = blockIdx.x * blockDim.x + threadIdx.x;
    int gs = gridDim.x * blockDim.x;
    for (int idx = i0; idx < HH * HH; idx += gs) {
        int k = idx / HH, j = idx % HH;
        g_wfhP[idx] = make_float4(wf_hh[j * HH + k], wf_hh[(HH + j) * HH + k],
                                  wf_hh[(2 * HH + j) * HH + k], 0.f);
        g_wbhP[idx] = make_float4(wb_hh[j * HH + k], wb_hh[(HH + j) * HH + k],
                                  wb_hh[(2 * HH + j) * HH + k], 0.f);
        g_sfhP[idx] = make_float4(sf_hh[j * HH + k], sf_hh[(HH + j) * HH + k],
                                  sf_hh[(2 * HH + j) * HH + k], 0.f);
        g_sbhP[idx] = make_float4(sb_hh[j * HH + k], sb_hh[(HH + j) * HH + k],
                                  sb_hh[(2 * HH + j) * HH + k], 0.f);
    }
    for (int s = i0; s < NS; s += gs) {
        int c = 0;
        for (int t = 0; t < TW; t++) c += (x[s * TW + t] != 0);
        g_slen[s] = c;
    }
    for (int i = i0; i < NS * HH; i += gs) { g_hf[i] = 0.f; g_hb[i] = 0.f; }
    for (int i = i0; i < NS * 2 * HH; i += gs) g_pool[i] = 0.f;
    for (int i = i0; i < ND * HH; i += gs) { g_hsf[i] = 0.f; g_hsb[i] = 0.f; }
    for (int i = i0; i < ND * 2 * HH; i += gs) g_poold[i] = 0.f;
}

__global__ void k_div() {
    int i = blockIdx.x * blockDim.x + threadIdx.x;
    if (i < NS * 2 * HH) {
        int b = i / (2 * HH);
        int l = g_slen[b];
        g_pool[i] = l ? g_pool[i] / (float)l : 0.f;
    }
}

__global__ void k_scan(const int* __restrict__ dl) {
    if (threadIdx.x == 0) {
        int a = 0;
        for (int i = 0; i < ND; i++) { g_offs[i] = a; a += dl[i]; }
    }
}

__global__ __launch_bounds__(128) void k_final(const int* __restrict__ dl,
                                               const float* __restrict__ doc_w,
                                               const float* __restrict__ doc_b,
                                               const float* __restrict__ sent_w,
                                               const float* __restrict__ sent_b,
                                               float* __restrict__ out) {
    __shared__ float d[2 * HH];
    __shared__ float redw[4];
    int doc = blockIdx.x, tid = threadIdx.x;
    int l = dl[doc];
    for (int f = tid; f < 2 * HH; f += 128) {
        float v = g_poold[doc * 2 * HH + f];
        d[f] = l ? v / (float)l : 0.f;
    }
    __syncthreads();
    for (int r = 0; r < 11; r++) {
        const float* w = (r == 0) ? doc_w : sent_w + (r - 1) * 2 * HH;
        float p = 0.f;
        for (int f = tid; f < 2 * HH; f += 128) p += d[f] * w[f];
        for (int o = 16; o; o >>= 1) p += __shfl_down_sync(0xFFFFFFFFu, p, o);
        if ((tid & 31) == 0) redw[tid >> 5] = p;
        __syncthreads();
        if (tid == 0) {
            float s = redw[0] + redw[1] + redw[2] + redw[3];
            if (r == 0) out[doc] = sigmoidf_(s + doc_b[0]);
            else if (r - 1 < l) out[ND + g_offs[doc] + (r - 1)] = sigmoidf_(s + sent_b[r - 1]);
        }
        __syncthreads();
    }
}

// ---------------- host ----------------
extern "C" void kernel_launch(void* const* d_in, const int* in_sizes, int n_in,
                              void* d_out, int out_size) {
    int base = (n_in >= 24) ? 1 : 0;  // doc_nums scalar present or not
    const int*   x        = (const int*)d_in[0];
    const int*   doc_lens = (const int*)d_in[1 + base];
    const float* emb      = (const float*)d_in[2 + base];
    const float* wf_ih    = (const float*)d_in[3 + base];
    const float* wf_hh    = (const float*)d_in[4 + base];
    const float* wf_bi    = (const float*)d_in[5 + base];
    const float* wf_bh    = (const float*)d_in[6 + base];
    const float* wb_ih    = (const float*)d_in[7 + base];
    const float* wb_hh    = (const float*)d_in[8 + base];
    const float* wb_bi    = (const float*)d_in[9 + base];
    const float* wb_bh    = (const float*)d_in[10 + base];
    const float* sf_ih    = (const float*)d_in[11 + base];
    const float* sf_hh    = (const float*)d_in[12 + base];
    const float* sf_bi    = (const float*)d_in[13 + base];
    const float* sf_bh    = (const float*)d_in[14 + base];
    const float* sb_ih    = (const float*)d_in[15 + base];
    const float* sb_hh    = (const float*)d_in[16 + base];
    const float* sb_bi    = (const float*)d_in[17 + base];
    const float* sb_bh    = (const float*)d_in[18 + base];
    const float* doc_w    = (const float*)d_in[19 + base];
    const float* doc_b    = (const float*)d_in[20 + base];
    const float* sent_w   = (const float*)d_in[21 + base];
    const float* sent_b   = (const float*)d_in[22 + base];
    float* out = (float*)d_out;

    float *P, *gxs, *pool;
    cudaGetSymbolAddress((void**)&P, g_P);
    cudaGetSymbolAddress((void**)&gxs, g_gxs);
    cudaGetSymbolAddress((void**)&pool, g_pool);

    k_prep<<<256, 256>>>(x, wf_hh, wb_hh, sf_hh, sb_hh);

    // P = emb @ [wf_ih; wb_ih]^T   (50000 x 1200)
    dim3 gP((600 + 63) / 64, (VOC + 127) / 128);
    gemm_bt<<<gP, 256>>>(emb, wf_ih, P, VOC, 600, DD, GXW);
    gemm_bt<<<gP, 256>>>(emb, wb_ih, P + 600, VOC, 600, DD, GXW);

    // word-level BiGRU: 50 steps  (BROWS=20 -> 128x2 blocks, 2 blocks/SM)
    dim3 gW((NS + 19) / 20, 2);
    for (int t = 0; t < TW; t++)
        gru_step<20, true, 2><<<gW, 256>>>(x, doc_lens, wf_bi, wf_bh, wb_bi, wb_bh, t);

    k_div<<<(NS * 2 * HH + 255) / 256, 256>>>();

    // sentence-level gates: gxs = s @ [sf_ih; sb_ih]^T   (2560 x 1200, K=400)
    dim3 gS((600 + 63) / 64, (NS + 127) / 128);
    gemm_bt<<<gS, 256>>>(pool, sf_ih, gxs, NS, 600, 2 * HH, GXW);
    gemm_bt<<<gS, 256>>>(pool, sb_ih, gxs + 600, NS, 600, 2 * HH, GXW);

    // sentence-level BiGRU: 10 steps
    dim3 gD((ND + 7) / 8, 2);
    for (int t = 0; t < DT; t++)
        gru_step<8, false, 1><<<gD, 256>>>(nullptr, doc_lens, sf_bi, sf_bh, sb_bi, sb_bh, t);

    k_scan<<<1, 32>>>(doc_lens);
    k_final<<<ND, 128>>>(doc_lens, doc_w, doc_b, sent_w, sent_b, out);
}

// round 5
// speedup vs baseline: 1.5536x; 1.2038x over previous
#include <cuda_runtime.h>
#include <math.h>

#define HH   200
#define DD   300
#define TW   50
#define NS   2560
#define ND   256
#define DT   10
#define GG   600
#define GXW  1200
#define VOC  50000

// ---------------- device scratch ----------------
__device__ float g_P[VOC * GXW];        // emb @ [wf_ih; wb_ih]^T
__device__ float g_gxs[NS * GXW];       // sentence-level input gates
// packed recurrent weights: [k][j] -> float4(w_r, w_z, w_n, 0)
__device__ float4 g_wfhP[HH * HH];
__device__ float4 g_wbhP[HH * HH];
__device__ float4 g_sfhP[HH * HH];
__device__ float4 g_sbhP[HH * HH];
__device__ float g_pool[NS * 2 * HH];
__device__ float g_poold[ND * 2 * HH];
__device__ int   g_slen[NS];
__device__ int   g_offs[ND];

// ---------------- helpers ----------------
typedef unsigned long long ull;
__device__ __forceinline__ ull pack1(float a) {
    ull r; asm("mov.b64 %0, {%1, %1};" : "=l"(r) : "f"(a)); return r;
}
__device__ __forceinline__ void fma2(ull& d, ull a, ull b) {
    asm("fma.rn.f32x2 %0, %1, %2, %0;" : "+l"(d) : "l"(a), "l"(b));
}
__device__ __forceinline__ void unpack2(ull v, float& a, float& b) {
    asm("mov.b64 {%0, %1}, %2;" : "=f"(a), "=f"(b) : "l"(v));
}
__device__ __forceinline__ float sigmoidf_(float x) {
    return __fdividef(1.f, 1.f + __expf(-x));
}
__device__ __forceinline__ float tanhf_(float x) {
    return 2.f * __fdividef(1.f, 1.f + __expf(-2.f * x)) - 1.f;
}

// ---------------- C[M,N](ldc) = A[M,K] @ B[N,K]^T  (fp32, f32x2) ----------------
__global__ __launch_bounds__(256) void gemm_bt(const float* __restrict__ A,
                                               const float* __restrict__ B,
                                               float* __restrict__ C,
                                               int M, int N, int K, int ldc) {
    __shared__ __align__(16) float As[20][132];
    __shared__ __align__(16) float Bs[20][68];
    int tid = threadIdx.x;
    int mb = blockIdx.y * 128, nb = blockIdx.x * 64;
    int tn = tid & 15, tm = tid >> 4;

    ull acc[4][4];
#pragma unroll
    for (int i = 0; i < 4; i++)
#pragma unroll
        for (int j = 0; j < 4; j++) acc[i][j] = 0ull;

    for (int k0 = 0; k0 < K; k0 += 20) {
#pragma unroll
        for (int l = 0; l < 10; l++) {
            int idx = tid + l * 256;
            int m = idx / 20, k = idx % 20;
            int gm = mb + m;
            As[k][m] = (gm < M) ? A[(size_t)gm * K + k0 + k] : 0.f;
        }
#pragma unroll
        for (int l = 0; l < 5; l++) {
            int idx = tid + l * 256;
            int n = idx / 20, k = idx % 20;
            int gn = nb + n;
            Bs[k][n] = (gn < N) ? B[(size_t)gn * K + k0 + k] : 0.f;
        }
        __syncthreads();
#pragma unroll
        for (int k = 0; k < 20; k++) {
            ulonglong2 a01 = *(const ulonglong2*)&As[k][tm * 8];
            ulonglong2 a23 = *(const ulonglong2*)&As[k][tm * 8 + 4];
            float4 bv = *(const float4*)&Bs[k][tn * 4];
            ull b0 = pack1(bv.x), b1 = pack1(bv.y), b2 = pack1(bv.z), b3 = pack1(bv.w);
            ull av[4] = {a01.x, a01.y, a23.x, a23.y};
#pragma unroll
            for (int i = 0; i < 4; i++) {
                fma2(acc[i][0], av[i], b0);
                fma2(acc[i][1], av[i], b1);
                fma2(acc[i][2], av[i], b2);
                fma2(acc[i][3], av[i], b3);
            }
        }
        __syncthreads();
    }
    int n0 = nb + tn * 4;
    if (n0 < N) {
#pragma unroll
        for (int i = 0; i < 4; i++) {
            int r0 = mb + tm * 8 + 2 * i;
            float v[2][4];
            unpack2(acc[i][0], v[0][0], v[1][0]);
            unpack2(acc[i][1], v[0][1], v[1][1]);
            unpack2(acc[i][2], v[0][2], v[1][2]);
            unpack2(acc[i][3], v[0][3], v[1][3]);
#pragma unroll
            for (int l = 0; l < 2; l++)
                if (r0 + l < M)
                    *(float4*)&C[(size_t)(r0 + l) * ldc + n0] =
                        make_float4(v[l][0], v[l][1], v[l][2], v[l][3]);
        }
    }
}

// ---------------- persistent GRU over all timesteps ----------------
// Each block owns BROWS rows for the whole sequence; h lives in SMEM.
// NR must be divisible by BROWS (2560/20, 256/8 -> exact, no guards).
template <int BROWS, bool WORD>
__global__ __launch_bounds__(256, 2) void gru_seq(
    const int* __restrict__ toks, const int* __restrict__ dlens,
    const float* __restrict__ bi_f, const float* __restrict__ bh_f,
    const float* __restrict__ bi_b, const float* __restrict__ bh_b) {
    constexpr int BP = BROWS / 2;
    constexpr int TLEN = WORD ? TW : DT;
    const float* gxsrc = WORD ? g_P : g_gxs;
    float* poolg = WORD ? g_pool : g_poold;

    __shared__ __align__(16) float2 hsT[HH][BP];   // [k][pair]
    __shared__ float pool_s[BROWS][HH];
    __shared__ int gxb[TLEN][BROWS];
    __shared__ int sln[BROWS];

    int dir = blockIdx.y;
    int b0 = blockIdx.x * BROWS;
    const float4* wP = WORD ? (dir ? g_wbhP : g_wfhP) : (dir ? g_sbhP : g_sfhP);
    const float* bi = dir ? bi_b : bi_f;
    const float* bh = dir ? bh_b : bh_f;
    int tid = threadIdx.x;

    // init h=0, pool=0, gather offsets, lens
    for (int idx = tid; idx < HH * BP; idx += 256)
        ((float2*)hsT)[idx] = make_float2(0.f, 0.f);
    for (int idx = tid; idx < BROWS * HH; idx += 256)
        ((float*)pool_s)[idx] = 0.f;
    for (int idx = tid; idx < TLEN * BROWS; idx += 256) {
        int t = idx / BROWS, b = idx % BROWS;
        int bg = b0 + b;
        int tt = dir ? (TLEN - 1 - t) : t;
        int row = WORD ? toks[bg * TLEN + tt] : (bg * TLEN + tt);
        gxb[t][b] = row * GXW + dir * GG;
    }
    if (tid < BROWS) sln[tid] = WORD ? g_slen[b0 + tid] : dlens[b0 + tid];
    __syncthreads();

    int j = tid;
    float bij0 = 0, bij1 = 0, bij2 = 0, bhj0 = 0, bhj1 = 0, bhj2 = 0;
    if (j < HH) {
        bij0 = bi[j]; bij1 = bi[HH + j]; bij2 = bi[2 * HH + j];
        bhj0 = bh[j]; bhj1 = bh[HH + j]; bhj2 = bh[2 * HH + j];
    }

    for (int t = 0; t < TLEN; t++) {
        int tt = dir ? (TLEN - 1 - t) : t;
        ull aR[BP], aZ[BP], aN[BP];
        float2 hold[BP];
        if (j < HH) {
#pragma unroll
            for (int p = 0; p < BP; p++) { aR[p] = 0; aZ[p] = 0; aN[p] = 0; }
            const float4* wp = wP + j;
            float4 wreg[4];
#pragma unroll
            for (int i = 0; i < 4; i++) wreg[i] = wp[i * HH];
#pragma unroll 4
            for (int k = 0; k < HH; k++) {
                float4 wc = wreg[k & 3];
                int kp = k + 4;
                if (kp < HH) wreg[k & 3] = wp[kp * HH];
                ull w0 = pack1(wc.x), w1 = pack1(wc.y), w2 = pack1(wc.z);
#pragma unroll
                for (int q = 0; q < BP / 2; q++) {
                    ulonglong2 hq = *(const ulonglong2*)&hsT[k][2 * q];
                    fma2(aR[2 * q], hq.x, w0);
                    fma2(aZ[2 * q], hq.x, w1);
                    fma2(aN[2 * q], hq.x, w2);
                    fma2(aR[2 * q + 1], hq.y, w0);
                    fma2(aZ[2 * q + 1], hq.y, w1);
                    fma2(aN[2 * q + 1], hq.y, w2);
                }
            }
#pragma unroll
            for (int p = 0; p < BP; p++) hold[p] = hsT[j][p];
        }
        __syncthreads();   // all reads of hsT done
        if (j < HH) {
#pragma unroll
            for (int p = 0; p < BP; p++) {
                float hr[2], hz[2], hn[2], hnew[2];
                unpack2(aR[p], hr[0], hr[1]);
                unpack2(aZ[p], hz[0], hz[1]);
                unpack2(aN[p], hn[0], hn[1]);
#pragma unroll
                for (int l = 0; l < 2; l++) {
                    int b = 2 * p + l;
                    const float* gx = gxsrc + gxb[t][b];
                    float r = sigmoidf_(gx[j] + bij0 + hr[l] + bhj0);
                    float z = sigmoidf_(gx[HH + j] + bij1 + hz[l] + bhj1);
                    float nn = tanhf_(gx[2 * HH + j] + bij2 + r * (hn[l] + bhj2));
                    float ho = l ? hold[p].y : hold[p].x;
                    hnew[l] = (1.f - z) * nn + z * ho;
                    if (tt < sln[b]) pool_s[b][j] += hnew[l];
                }
                hsT[j][p] = make_float2(hnew[0], hnew[1]);
            }
        }
        __syncthreads();   // new h visible
    }

    // pooled average writeback
    if (j < HH) {
#pragma unroll
        for (int b = 0; b < BROWS; b++) {
            int l = sln[b];
            float v = pool_s[b][j];
            poolg[(size_t)(b0 + b) * (2 * HH) + dir * HH + j] =
                l ? v / (float)l : 0.f;
        }
    }
}

// ---------------- prep: weight packing, sent lens ----------------
__global__ void k_prep(const int* __restrict__ x,
                       const float* __restrict__ wf_hh, const float* __restrict__ wb_hh,
                       const float* __restrict__ sf_hh, const float* __restrict__ sb_hh) {
    int i0 = blockIdx.x * blockDim.x + threadIdx.x;
    int gs = gridDim.x * blockDim.x;
    for (int idx = i0; idx < HH * HH; idx += gs) {
        int k = idx / HH, j = idx % HH;
        g_wfhP[idx] = make_float4(wf_hh[j * HH + k], wf_hh[(HH + j) * HH + k],
                                  wf_hh[(2 * HH + j) * HH + k], 0.f);
        g_wbhP[idx] = make_float4(wb_hh[j * HH + k], wb_hh[(HH + j) * HH + k],
                                  wb_hh[(2 * HH + j) * HH + k], 0.f);
        g_sfhP[idx] = make_float4(sf_hh[j * HH + k], sf_hh[(HH + j) * HH + k],
                                  sf_hh[(2 * HH + j) * HH + k], 0.f);
        g_sbhP[idx] = make_float4(sb_hh[j * HH + k], sb_hh[(HH + j) * HH + k],
                                  sb_hh[(2 * HH + j) * HH + k], 0.f);
    }
    for (int s = i0; s < NS; s += gs) {
        int c = 0;
        for (int t = 0; t < TW; t++) c += (x[s * TW + t] != 0);
        g_slen[s] = c;
    }
}

__global__ void k_scan(const int* __restrict__ dl) {
    if (threadIdx.x == 0) {
        int a = 0;
        for (int i = 0; i < ND; i++) { g_offs[i] = a; a += dl[i]; }
    }
}

__global__ __launch_bounds__(128) void k_final(const int* __restrict__ dl,
                                               const float* __restrict__ doc_w,
                                               const float* __restrict__ doc_b,
                                               const float* __restrict__ sent_w,
                                               const float* __restrict__ sent_b,
                                               float* __restrict__ out) {
    __shared__ float d[2 * HH];
    __shared__ float redw[4];
    int doc = blockIdx.x, tid = threadIdx.x;
    int l = dl[doc];
    for (int f = tid; f < 2 * HH; f += 128)
        d[f] = g_poold[doc * 2 * HH + f];   // already averaged
    __syncthreads();
    for (int r = 0; r < 11; r++) {
        const float* w = (r == 0) ? doc_w : sent_w + (r - 1) * 2 * HH;
        float p = 0.f;
        for (int f = tid; f < 2 * HH; f += 128) p += d[f] * w[f];
        for (int o = 16; o; o >>= 1) p += __shfl_down_sync(0xFFFFFFFFu, p, o);
        if ((tid & 31) == 0) redw[tid >> 5] = p;
        __syncthreads();
        if (tid == 0) {
            float s = redw[0] + redw[1] + redw[2] + redw[3];
            if (r == 0) out[doc] = sigmoidf_(s + doc_b[0]);
            else if (r - 1 < l) out[ND + g_offs[doc] + (r - 1)] = sigmoidf_(s + sent_b[r - 1]);
        }
        __syncthreads();
    }
}

// ---------------- host ----------------
extern "C" void kernel_launch(void* const* d_in, const int* in_sizes, int n_in,
                              void* d_out, int out_size) {
    int base = (n_in >= 24) ? 1 : 0;  // doc_nums scalar present or not
    const int*   x        = (const int*)d_in[0];
    const int*   doc_lens = (const int*)d_in[1 + base];
    const float* emb      = (const float*)d_in[2 + base];
    const float* wf_ih    = (const float*)d_in[3 + base];
    const float* wf_hh    = (const float*)d_in[4 + base];
    const float* wf_bi    = (const float*)d_in[5 + base];
    const float* wf_bh    = (const float*)d_in[6 + base];
    const float* wb_ih    = (const float*)d_in[7 + base];
    const float* wb_hh    = (const float*)d_in[8 + base];
    const float* wb_bi    = (const float*)d_in[9 + base];
    const float* wb_bh    = (const float*)d_in[10 + base];
    const float* sf_ih    = (const float*)d_in[11 + base];
    const float* sf_hh    = (const float*)d_in[12 + base];
    const float* sf_bi    = (const float*)d_in[13 + base];
    const float* sf_bh    = (const float*)d_in[14 + base];
    const float* sb_ih    = (const float*)d_in[15 + base];
    const float* sb_hh    = (const float*)d_in[16 + base];
    const float* sb_bi    = (const float*)d_in[17 + base];
    const float* sb_bh    = (const float*)d_in[18 + base];
    const float* doc_w    = (const float*)d_in[19 + base];
    const float* doc_b    = (const float*)d_in[20 + base];
    const float* sent_w   = (const float*)d_in[21 + base];
    const float* sent_b   = (const float*)d_in[22 + base];
    float* out = (float*)d_out;

    float *P, *gxs, *pool;
    cudaGetSymbolAddress((void**)&P, g_P);
    cudaGetSymbolAddress((void**)&gxs, g_gxs);
    cudaGetSymbolAddress((void**)&pool, g_pool);

    k_prep<<<256, 256>>>(x, wf_hh, wb_hh, sf_hh, sb_hh);

    // P = emb @ [wf_ih; wb_ih]^T   (50000 x 1200)
    dim3 gP((600 + 63) / 64, (VOC + 127) / 128);
    gemm_bt<<<gP, 256>>>(emb, wf_ih, P, VOC, 600, DD, GXW);
    gemm_bt<<<gP, 256>>>(emb, wb_ih, P + 600, VOC, 600, DD, GXW);

    // word-level BiGRU: single persistent launch (128 x 2 blocks)
    gru_seq<20, true><<<dim3(NS / 20, 2), 256>>>(x, doc_lens, wf_bi, wf_bh, wb_bi, wb_bh);

    // sentence-level gates: gxs = s @ [sf_ih; sb_ih]^T   (2560 x 1200, K=400)
    dim3 gS((600 + 63) / 64, (NS + 127) / 128);
    gemm_bt<<<gS, 256>>>(pool, sf_ih, gxs, NS, 600, 2 * HH, GXW);
    gemm_bt<<<gS, 256>>>(pool, sb_ih, gxs + 600, NS, 600, 2 * HH, GXW);

    // sentence-level BiGRU: single persistent launch (32 x 2 blocks)
    gru_seq<8, false><<<dim3(ND / 8, 2), 256>>>(nullptr, doc_lens, sf_bi, sf_bh, sb_bi, sb_bh);

    k_scan<<<1, 32>>>(doc_lens);
    k_final<<<ND, 128>>>(doc_lens, doc_w, doc_b, sent_w, sent_b, out);
}